// round 6
// baseline (speedup 1.0000x reference)
#include <cuda_runtime.h>
#include <cstdint>

#define SQ 512
#define BB 64
#define EE 128
#define HH 256
#define NG 1024   // 4*H

// ---------------- scratch (static device memory; no allocations) ----------------
__device__ float g_x [SQ*BB*EE];   // embedded inputs           16 MB
__device__ float g_xg[(size_t)SQ*BB*NG];  // forward input-gate proj  128 MB
__device__ float g_gb[BB*NG];      // backward first-step gates
__device__ float g_hf[BB*HH];      // final forward h
__device__ float g_hb[BB*HH];      // backward first-step h

__device__ __forceinline__ float sigf(float x)  { return 1.f/(1.f+__expf(-x)); }
__device__ __forceinline__ float tanhf_(float x){ return 1.f - 2.f/(__expf(2.f*x)+1.f); }

// ---------------- kernel 1: embedding gather ----------------
// one warp per (s,b) row; lane = float4 chunk of E=128
__global__ void k_embed(const int* __restrict__ seq, const float* __restrict__ emb,
                        float* __restrict__ x)
{
    int row  = blockIdx.x * 4 + (threadIdx.x >> 5);   // 0..32767
    int lane = threadIdx.x & 31;
    int idx  = seq[row];
    float4 v;
    if (idx == 0) v = make_float4(0.f, 0.f, 0.f, 0.f);
    else          v = ((const float4*)emb)[(size_t)idx * 32 + lane];
    ((float4*)x)[(size_t)row * 32 + lane] = v;
}

// ---------------- kernel 2: C[M,1024] = A[M,128] @ W[1024,128]^T + bias ----------------
// BM=BN=64, full K=128 in smem (k-major transposed tiles), 256 thr, 4x4 micro-tile
__global__ void __launch_bounds__(256)
k_gemm(const float* __restrict__ A, const float* __restrict__ W,
       const float* __restrict__ bias, float* __restrict__ C)
{
    extern __shared__ float sm[];
    float* As = sm;             // [128][68]  (k-major: As[k][m])
    float* Bs = sm + 128*68;    // [128][68]  (k-major: Bs[k][n])

    const int tid = threadIdx.x;
    const int gm0 = blockIdx.y * 64;
    const int gn0 = blockIdx.x * 64;

#pragma unroll
    for (int i = 0; i < 8; ++i) {
        int e   = tid + i * 256;
        int row = e >> 5;       // 0..63
        int kq  = e & 31;       // float4 column (K/4)
        float4 a = ((const float4*)A)[(size_t)(gm0 + row) * 32 + kq];
        As[(4*kq+0)*68 + row] = a.x;
        As[(4*kq+1)*68 + row] = a.y;
        As[(4*kq+2)*68 + row] = a.z;
        As[(4*kq+3)*68 + row] = a.w;
        float4 w = ((const float4*)W)[(size_t)(gn0 + row) * 32 + kq];
        Bs[(4*kq+0)*68 + row] = w.x;
        Bs[(4*kq+1)*68 + row] = w.y;
        Bs[(4*kq+2)*68 + row] = w.z;
        Bs[(4*kq+3)*68 + row] = w.w;
    }
    __syncthreads();

    const int tx = tid & 15, ty = tid >> 4;
    const int m0 = ty * 4, n0 = tx * 4;

    float acc[4][4];
#pragma unroll
    for (int j = 0; j < 4; ++j) {
        float bz = bias[gn0 + n0 + j];
#pragma unroll
        for (int i = 0; i < 4; ++i) acc[i][j] = bz;
    }

#pragma unroll 4
    for (int k = 0; k < 128; ++k) {
        float4 a4 = *(const float4*)&As[k*68 + m0];
        float4 b4 = *(const float4*)&Bs[k*68 + n0];
        float av[4] = {a4.x, a4.y, a4.z, a4.w};
        float bv[4] = {b4.x, b4.y, b4.z, b4.w};
#pragma unroll
        for (int i = 0; i < 4; ++i)
#pragma unroll
            for (int j = 0; j < 4; ++j)
                acc[i][j] = fmaf(av[i], bv[j], acc[i][j]);
    }

#pragma unroll
    for (int i = 0; i < 4; ++i) {
        float4 o = make_float4(acc[i][0], acc[i][1], acc[i][2], acc[i][3]);
        ((float4*)C)[(size_t)(gm0 + m0 + i) * 256 + ((gn0 + n0) >> 2)] = o;
    }
}

// ---------------- kernel 3: forward LSTM scan ----------------
// 16 clusters x 8 CTAs. Cluster = 4 batch elems; CTA = 32-hidden-unit slice.
// W_hh slice (128 rows x 256) resident in SMEM. h exchanged via DSMEM each step.
__global__ void __cluster_dims__(8,1,1) __launch_bounds__(128,1)
k_scan(const float* __restrict__ xg, const float* __restrict__ Whh,
       float* __restrict__ hout)
{
    extern __shared__ float sm[];
    float* Ws    = sm;                      // [128][260]
    float* hbuf  = sm + 128*260;            // [2][4][260]
    float* gates = hbuf + 2*4*260;          // [4 gate][4 b][32 j]

    const int tid   = threadIdx.x;
    const int rank  = blockIdx.x & 7;       // CTA rank in cluster (1-D, contiguous)
    const int bg    = blockIdx.x >> 3;      // batch group 0..15
    const int jbase = rank << 5;            // hidden slice base

    const int gq = tid >> 5;                // phase1: gate idx / phase2: batch idx
    const int jj = tid & 31;

    // load W_hh slice: local row r -> global gate row (r>>5)*256 + jbase + (r&31)
#pragma unroll
    for (int it = 0; it < 64; ++it) {
        int idx  = tid + it * 128;          // 0..8191
        int r    = idx >> 6;
        int kq   = idx & 63;
        int grow = ((r >> 5) << 8) + jbase + (r & 31);
        float4 w = ((const float4*)Whh)[(size_t)grow * 64 + kq];
        *(float4*)(Ws + r*260 + 4*kq) = w;
    }
    for (int idx = tid; idx < 4*260; idx += 128) hbuf[idx] = 0.f;   // h buffer 0
    float creg = 0.f;

    const int    wrowoff = (gq*32 + jj) * 260;
    const int    grow_g  = gq*256 + jbase + jj;          // gate row 0..1023
    const float* xg_t    = xg + (size_t)(bg*4) * NG + grow_g;

    __syncthreads();
    asm volatile("barrier.cluster.arrive.aligned;" ::: "memory");
    asm volatile("barrier.cluster.wait.aligned;"   ::: "memory");

    uint32_t hbase = (uint32_t)__cvta_generic_to_shared(hbuf);

    // prefetch xg for t = 0
    float nx0 = xg_t[0*NG], nx1 = xg_t[1*NG], nx2 = xg_t[2*NG], nx3 = xg_t[3*NG];

    for (int t = 0; t < SQ; ++t) {
        const float* hR   = hbuf + (t & 1) * (4*260);
        const int    bufW = (t & 1) ^ 1;

        float a0 = nx0, a1 = nx1, a2 = nx2, a3 = nx3;

#pragma unroll 8
        for (int kc = 0; kc < 64; ++kc) {
            float4 w4 = *(const float4*)(Ws + wrowoff + 4*kc);
            float4 h0 = *(const float4*)(hR + 0*260 + 4*kc);
            float4 h1 = *(const float4*)(hR + 1*260 + 4*kc);
            float4 h2 = *(const float4*)(hR + 2*260 + 4*kc);
            float4 h3 = *(const float4*)(hR + 3*260 + 4*kc);
            a0 = fmaf(w4.x,h0.x, fmaf(w4.y,h0.y, fmaf(w4.z,h0.z, fmaf(w4.w,h0.w, a0))));
            a1 = fmaf(w4.x,h1.x, fmaf(w4.y,h1.y, fmaf(w4.z,h1.z, fmaf(w4.w,h1.w, a1))));
            a2 = fmaf(w4.x,h2.x, fmaf(w4.y,h2.y, fmaf(w4.z,h2.z, fmaf(w4.w,h2.w, a2))));
            a3 = fmaf(w4.x,h3.x, fmaf(w4.y,h3.y, fmaf(w4.z,h3.z, fmaf(w4.w,h3.w, a3))));
        }
        gates[gq*128 + 0*32 + jj] = a0;
        gates[gq*128 + 1*32 + jj] = a1;
        gates[gq*128 + 2*32 + jj] = a2;
        gates[gq*128 + 3*32 + jj] = a3;

        // prefetch next step's xg (hides DRAM latency under phase2 + barrier)
        if (t + 1 < SQ) {
            const float* p = xg_t + (size_t)(t + 1) * BB * NG;
            nx0 = p[0*NG]; nx1 = p[1*NG]; nx2 = p[2*NG]; nx3 = p[3*NG];
        }
        __syncthreads();

        // phase 2: thread = (b = gq, j = jj)
        float gi = gates[0*128 + gq*32 + jj];
        float gf = gates[1*128 + gq*32 + jj];
        float gg = gates[2*128 + gq*32 + jj];
        float go = gates[3*128 + gq*32 + jj];
        float iv = sigf(gi), fv = sigf(gf), cv = tanhf_(gg), ov = sigf(go);
        creg = fv * creg + iv * cv;
        float hv = ov * tanhf_(creg);

        // broadcast h value to all 8 CTAs' h buffers (including self) via DSMEM
        uint32_t myaddr = hbase + (uint32_t)(((bufW*4 + gq)*260 + (jbase + jj)) * 4);
#pragma unroll
        for (int r = 0; r < 8; ++r) {
            uint32_t pa;
            asm volatile("mapa.shared::cluster.u32 %0, %1, %2;" : "=r"(pa) : "r"(myaddr), "r"(r));
            asm volatile("st.shared::cluster.f32 [%0], %1;" :: "r"(pa), "f"(hv));
        }
        if (t == SQ - 1)
            hout[(size_t)(bg*4 + gq) * HH + jbase + jj] = hv;

        asm volatile("barrier.cluster.arrive.aligned;" ::: "memory");  // release
        asm volatile("barrier.cluster.wait.aligned;"   ::: "memory");  // acquire
    }
}

// ---------------- kernel 4: backward first-step (h0=c0=0 -> f-gate irrelevant) ----------------
__global__ void k_hback(const float* __restrict__ gb, float* __restrict__ hb)
{
    int i = blockIdx.x * 256 + threadIdx.x;   // 0..16383
    int b = i >> 8, j = i & 255;
    const float* g = gb + (size_t)b * NG;
    float iv = sigf(g[j]);
    float gv = tanhf_(g[512 + j]);
    float ov = sigf(g[768 + j]);
    float c  = iv * gv;
    hb[i] = ov * tanhf_(c);
}

// ---------------- kernel 5: output head ----------------
__global__ void k_out(const float* __restrict__ hf, const float* __restrict__ hb,
                      const float* __restrict__ Wout, const float* __restrict__ bout,
                      float* __restrict__ out)
{
    int b = threadIdx.x;   // 64 threads
    float acc = bout[0];
#pragma unroll 8
    for (int j = 0; j < HH; ++j)
        acc += hf[b*HH + j] * Wout[j] + hb[b*HH + j] * Wout[HH + j];
    out[b] = sigf(acc);
}

// ---------------- launch ----------------
extern "C" void kernel_launch(void* const* d_in, const int* in_sizes, int n_in,
                              void* d_out, int out_size)
{
    (void)in_sizes; (void)n_in; (void)out_size;
    const int*   seq  = (const int*)  d_in[0];
    const float* emb  = (const float*)d_in[1];
    const float* Wihf = (const float*)d_in[2];
    const float* Whhf = (const float*)d_in[3];
    const float* bf   = (const float*)d_in[4];
    const float* Wihb = (const float*)d_in[5];
    const float* Whhb = (const float*)d_in[6];
    const float* bb   = (const float*)d_in[7];
    const float* Wout = (const float*)d_in[8];
    const float* bout = (const float*)d_in[9];
    (void)Whhb;
    float* out = (float*)d_out;

    float *x, *xgf, *gb, *hf, *hb;
    cudaGetSymbolAddress((void**)&x,   g_x);
    cudaGetSymbolAddress((void**)&xgf, g_xg);
    cudaGetSymbolAddress((void**)&gb,  g_gb);
    cudaGetSymbolAddress((void**)&hf,  g_hf);
    cudaGetSymbolAddress((void**)&hb,  g_hb);

    const int SMEM_GEMM = 2 * 128 * 68 * 4;                      // 69632
    const int SMEM_SCAN = (128*260 + 2*4*260 + 512) * 4;         // 143488
    cudaFuncSetAttribute(k_gemm, cudaFuncAttributeMaxDynamicSharedMemorySize, SMEM_GEMM);
    cudaFuncSetAttribute(k_scan, cudaFuncAttributeMaxDynamicSharedMemorySize, SMEM_SCAN);

    // 1. embed
    k_embed<<<SQ*BB/4, 128>>>(seq, emb, x);
    // 2. forward input projection xg_f (M = S*B = 32768)
    dim3 g2(16, SQ*BB/64);
    k_gemm<<<g2, 256, SMEM_GEMM>>>(x, Wihf, bf, xgf);
    // 3. backward first-step gates (M = 64, A = x[S-1])
    dim3 g2b(16, 1);
    k_gemm<<<g2b, 256, SMEM_GEMM>>>(x + (size_t)(SQ-1)*BB*EE, Wihb, bb, gb);
    k_hback<<<64, 256>>>(gb, hb);
    // 4. sequential forward scan (16 independent clusters of 8 CTAs)
    k_scan<<<128, 128, SMEM_SCAN>>>(xgf, Whhf, hf);
    // 5. output head
    k_out<<<1, 64>>>(hf, hb, Wout, bout, out);
}

// round 7
// speedup vs baseline: 1.2206x; 1.2206x over previous
#include <cuda_runtime.h>
#include <cstdint>
#include <cstring>

#define SQ 512
#define BB 64
#define EE 128
#define HH 256
#define NG 1024   // 4*H

// ---------------- scratch (static device memory; no allocations) ----------------
__device__ float g_x [SQ*BB*EE];          // embedded inputs          16 MB
__device__ float g_xg[(size_t)SQ*BB*NG];  // forward input-gate proj  128 MB
__device__ float g_gb[BB*NG];             // backward first-step gates
__device__ float g_hf[BB*HH];             // final forward h
__device__ float g_hb[BB*HH];             // backward first-step h

typedef unsigned long long ull;

__device__ __forceinline__ void fma2(ull& d, ull a, ull b) {
    asm("fma.rn.f32x2 %0, %1, %2, %0;" : "+l"(d) : "l"(a), "l"(b));
}
__device__ __forceinline__ ull pk(float x, float y) {
    float2 f = make_float2(x, y); ull v; memcpy(&v, &f, 8); return v;
}
__device__ __forceinline__ float2 unpk(ull v) {
    float2 f; memcpy(&f, &v, 8); return f;
}
__device__ __forceinline__ float sigf(float x)  { return 1.f/(1.f+__expf(-x)); }
__device__ __forceinline__ float tanhf_(float x){ return 1.f - 2.f/(__expf(2.f*x)+1.f); }

// ---------------- kernel 1: embedding gather ----------------
__global__ void k_embed(const int* __restrict__ seq, const float* __restrict__ emb,
                        float* __restrict__ x)
{
    int row  = blockIdx.x * 4 + (threadIdx.x >> 5);   // 0..32767
    int lane = threadIdx.x & 31;
    int idx  = seq[row];
    float4 v;
    if (idx == 0) v = make_float4(0.f, 0.f, 0.f, 0.f);
    else          v = ((const float4*)emb)[(size_t)idx * 32 + lane];
    ((float4*)x)[(size_t)row * 32 + lane] = v;
}

// ---------------- kernel 2: C[M,1024] = A[M,128] @ W[1024,128]^T + bias ----------------
// BM=BN=64, full K=128 in smem (k-major), 256 thr, 4x4 micro-tile, f32x2 FMA
__global__ void __launch_bounds__(256)
k_gemm(const float* __restrict__ A, const float* __restrict__ W,
       const float* __restrict__ bias, float* __restrict__ C)
{
    extern __shared__ float sm[];
    float* As = sm;             // [128][68]  (k-major: As[k][m])
    float* Bs = sm + 128*68;    // [128][68]  (k-major: Bs[k][n])

    const int tid = threadIdx.x;
    const int gm0 = blockIdx.y * 64;
    const int gn0 = blockIdx.x * 64;

#pragma unroll
    for (int i = 0; i < 8; ++i) {
        int e   = tid + i * 256;
        int row = e >> 5;
        int kq  = e & 31;
        float4 a = ((const float4*)A)[(size_t)(gm0 + row) * 32 + kq];
        As[(4*kq+0)*68 + row] = a.x;
        As[(4*kq+1)*68 + row] = a.y;
        As[(4*kq+2)*68 + row] = a.z;
        As[(4*kq+3)*68 + row] = a.w;
        float4 w = ((const float4*)W)[(size_t)(gn0 + row) * 32 + kq];
        Bs[(4*kq+0)*68 + row] = w.x;
        Bs[(4*kq+1)*68 + row] = w.y;
        Bs[(4*kq+2)*68 + row] = w.z;
        Bs[(4*kq+3)*68 + row] = w.w;
    }
    __syncthreads();

    const int tx = tid & 15, ty = tid >> 4;
    const int m0 = ty * 4, n0 = tx * 4;

    float b0 = bias[gn0+n0+0], b1 = bias[gn0+n0+1];
    float b2 = bias[gn0+n0+2], b3 = bias[gn0+n0+3];
    ull acc[4][2];
#pragma unroll
    for (int i = 0; i < 4; ++i) { acc[i][0] = pk(b0,b1); acc[i][1] = pk(b2,b3); }

#pragma unroll 4
    for (int k = 0; k < 128; ++k) {
        float4 a4 = *(const float4*)&As[k*68 + m0];
        ulonglong2 bb = *(const ulonglong2*)&Bs[k*68 + n0];
        ull ad;
        ad = pk(a4.x, a4.x); fma2(acc[0][0], ad, bb.x); fma2(acc[0][1], ad, bb.y);
        ad = pk(a4.y, a4.y); fma2(acc[1][0], ad, bb.x); fma2(acc[1][1], ad, bb.y);
        ad = pk(a4.z, a4.z); fma2(acc[2][0], ad, bb.x); fma2(acc[2][1], ad, bb.y);
        ad = pk(a4.w, a4.w); fma2(acc[3][0], ad, bb.x); fma2(acc[3][1], ad, bb.y);
    }

#pragma unroll
    for (int i = 0; i < 4; ++i) {
        float2 lo = unpk(acc[i][0]), hi = unpk(acc[i][1]);
        float4 o = make_float4(lo.x, lo.y, hi.x, hi.y);
        ((float4*)C)[(size_t)(gm0 + m0 + i) * 256 + ((gn0 + n0) >> 2)] = o;
    }
}

// ---------------- kernel 3: forward LSTM scan ----------------
// 16 clusters x 8 CTAs, 256 thr. Cluster = 4 batch elems; CTA = 32 hidden units
// (128 gate rows). W_hh slice lives ENTIRELY in registers (128 regs/thread).
// Thread t: row-pair rp = t>>2 (rows 2rp,2rp+1), k-quarter kq = t&3 (64 k's).
// h exchanged via DSMEM each step; cross-kq reduce via shfl.
__global__ void __cluster_dims__(8,1,1) __launch_bounds__(256,1)
k_scan(const float* __restrict__ xg, const float* __restrict__ Whh,
       float* __restrict__ hout)
{
    __shared__ __align__(16) float hbuf[2*4*4*68];   // [buf][b][kq][68] skewed
    __shared__ float gates[4*128];                   // [b][gate-row r]

    const int tid   = threadIdx.x;
    const int rank  = blockIdx.x & 7;
    const int bg    = blockIdx.x >> 3;
    const int jbase = rank << 5;

    const int rp = tid >> 2;           // 0..63
    const int kq = tid & 3;            // k in [64*kq, 64*kq+64)
    const int r0 = rp * 2, r1 = r0 + 1;
    const int grow0 = ((r0 >> 5) << 8) + jbase + (r0 & 31);
    const int grow1 = ((r1 >> 5) << 8) + jbase + (r1 & 31);

    // ---- W_hh slice into registers: 2 rows x 64 k = 64 packed pairs ----
    ull w0[32], w1[32];
    {
        const float4* p0 = (const float4*)(Whh + (size_t)grow0 * HH + kq * 64);
        const float4* p1 = (const float4*)(Whh + (size_t)grow1 * HH + kq * 64);
#pragma unroll
        for (int i = 0; i < 16; ++i) {
            float4 a = p0[i]; w0[2*i] = pk(a.x, a.y); w0[2*i+1] = pk(a.z, a.w);
            float4 b = p1[i]; w1[2*i] = pk(b.x, b.y); w1[2*i+1] = pk(b.z, b.w);
        }
    }
    for (int i = tid; i < 2*4*4*68; i += 256) hbuf[i] = 0.f;

    // ---- phase-2 constants (threads 0..127 act as (b2, j2)) ----
    const int b2 = (tid >> 5) & 3;
    const int j2 = tid & 31;
    float creg = 0.f;
    uint32_t ra0[8], ra1[8];   // precomputed DSMEM addrs for both buffers
    {
        int jg  = jbase + j2;
        int kqj = jg >> 6, idxj = jg & 63;
        uint32_t base = (uint32_t)__cvta_generic_to_shared(hbuf);
        uint32_t o0 = (uint32_t)((((0*4 + b2)*4 + kqj)*68 + idxj) * 4);
        uint32_t o1 = (uint32_t)((((1*4 + b2)*4 + kqj)*68 + idxj) * 4);
#pragma unroll
        for (int r = 0; r < 8; ++r) {
            asm("mapa.shared::cluster.u32 %0, %1, %2;" : "=r"(ra0[r]) : "r"(base+o0), "r"(r));
            asm("mapa.shared::cluster.u32 %0, %1, %2;" : "=r"(ra1[r]) : "r"(base+o1), "r"(r));
        }
    }

    // xg pointers for (b = 4bg+kq, rows grow0/grow1); advance by BB*NG per step
    const float* xp0 = xg + (size_t)(4*bg + kq) * NG + grow0;
    const float* xp1 = xg + (size_t)(4*bg + kq) * NG + grow1;
    float nx0 = xp0[0], nx1 = xp1[0];

    __syncthreads();
    asm volatile("barrier.cluster.arrive.aligned;" ::: "memory");
    asm volatile("barrier.cluster.wait.aligned;"   ::: "memory");

#pragma unroll 1
    for (int t = 0; t < SQ; ++t) {
        const float* hq = hbuf + (t & 1) * 1088 + kq * 68;

        ull a00=0,a01=0,a02=0,a03=0, a10=0,a11=0,a12=0,a13=0;
#pragma unroll
        for (int c = 0; c < 16; ++c) {
            ulonglong2 h0 = *(const ulonglong2*)(hq + 0*272 + 4*c);
            ulonglong2 h1 = *(const ulonglong2*)(hq + 1*272 + 4*c);
            ulonglong2 h2 = *(const ulonglong2*)(hq + 2*272 + 4*c);
            ulonglong2 h3 = *(const ulonglong2*)(hq + 3*272 + 4*c);
            ull wa = w0[2*c], wb = w0[2*c+1], wc = w1[2*c], wd = w1[2*c+1];
            fma2(a00, wa, h0.x); fma2(a00, wb, h0.y);
            fma2(a01, wa, h1.x); fma2(a01, wb, h1.y);
            fma2(a02, wa, h2.x); fma2(a02, wb, h2.y);
            fma2(a03, wa, h3.x); fma2(a03, wb, h3.y);
            fma2(a10, wc, h0.x); fma2(a10, wd, h0.y);
            fma2(a11, wc, h1.x); fma2(a11, wd, h1.y);
            fma2(a12, wc, h2.x); fma2(a12, wd, h2.y);
            fma2(a13, wc, h3.x); fma2(a13, wd, h3.y);
        }

        // current xg, then prefetch next step's (hides DRAM under reduce/phase2)
        float cx0 = nx0, cx1 = nx1;
        if (t + 1 < SQ) {
            nx0 = xp0[(size_t)(t + 1) * (BB * NG)];
            nx1 = xp1[(size_t)(t + 1) * (BB * NG)];
        }

        // cross-kq reduction (4 lanes per group)
        float2 f;
        f = unpk(a00); float s00 = f.x + f.y;
        f = unpk(a01); float s01 = f.x + f.y;
        f = unpk(a02); float s02 = f.x + f.y;
        f = unpk(a03); float s03 = f.x + f.y;
        f = unpk(a10); float s10 = f.x + f.y;
        f = unpk(a11); float s11 = f.x + f.y;
        f = unpk(a12); float s12 = f.x + f.y;
        f = unpk(a13); float s13 = f.x + f.y;
        s00 += __shfl_xor_sync(0xffffffffu, s00, 1); s00 += __shfl_xor_sync(0xffffffffu, s00, 2);
        s01 += __shfl_xor_sync(0xffffffffu, s01, 1); s01 += __shfl_xor_sync(0xffffffffu, s01, 2);
        s02 += __shfl_xor_sync(0xffffffffu, s02, 1); s02 += __shfl_xor_sync(0xffffffffu, s02, 2);
        s03 += __shfl_xor_sync(0xffffffffu, s03, 1); s03 += __shfl_xor_sync(0xffffffffu, s03, 2);
        s10 += __shfl_xor_sync(0xffffffffu, s10, 1); s10 += __shfl_xor_sync(0xffffffffu, s10, 2);
        s11 += __shfl_xor_sync(0xffffffffu, s11, 1); s11 += __shfl_xor_sync(0xffffffffu, s11, 2);
        s12 += __shfl_xor_sync(0xffffffffu, s12, 1); s12 += __shfl_xor_sync(0xffffffffu, s12, 2);
        s13 += __shfl_xor_sync(0xffffffffu, s13, 1); s13 += __shfl_xor_sync(0xffffffffu, s13, 2);

        // lane kq writes (b = kq, rows r0,r1), adding its xg values
        float g0, g1;
        if      (kq == 0) { g0 = s00; g1 = s10; }
        else if (kq == 1) { g0 = s01; g1 = s11; }
        else if (kq == 2) { g0 = s02; g1 = s12; }
        else              { g0 = s03; g1 = s13; }
        *(float2*)&gates[kq*128 + r0] = make_float2(g0 + cx0, g1 + cx1);

        __syncthreads();

        if (tid < 128) {
            float gi = gates[b2*128 +  0 + j2];
            float gf = gates[b2*128 + 32 + j2];
            float gg = gates[b2*128 + 64 + j2];
            float go = gates[b2*128 + 96 + j2];
            float iv = sigf(gi), fv = sigf(gf), cv = tanhf_(gg), ov = sigf(go);
            creg = fv * creg + iv * cv;
            float hv = ov * tanhf_(creg);

            const bool useBuf1 = ((t & 1) == 0);   // write buf = (t&1)^1
#pragma unroll
            for (int r = 0; r < 8; ++r) {
                uint32_t ad = useBuf1 ? ra1[r] : ra0[r];
                asm volatile("st.shared::cluster.f32 [%0], %1;" :: "r"(ad), "f"(hv));
            }
            if (t == SQ - 1)
                hout[(size_t)(4*bg + b2) * HH + jbase + j2] = hv;
        }

        asm volatile("barrier.cluster.arrive.aligned;" ::: "memory");
        asm volatile("barrier.cluster.wait.aligned;"   ::: "memory");
    }
}

// ---------------- kernel 4: backward first-step (h0=c0=0) ----------------
__global__ void k_hback(const float* __restrict__ gb, float* __restrict__ hb)
{
    int i = blockIdx.x * 256 + threadIdx.x;   // 0..16383
    int b = i >> 8, j = i & 255;
    const float* g = gb + (size_t)b * NG;
    float iv = sigf(g[j]);
    float gv = tanhf_(g[512 + j]);
    float ov = sigf(g[768 + j]);
    float c  = iv * gv;
    hb[i] = ov * tanhf_(c);
}

// ---------------- kernel 5: output head ----------------
__global__ void k_out(const float* __restrict__ hf, const float* __restrict__ hb,
                      const float* __restrict__ Wout, const float* __restrict__ bout,
                      float* __restrict__ out)
{
    int b = threadIdx.x;   // 64 threads
    float acc = bout[0];
#pragma unroll 8
    for (int j = 0; j < HH; ++j)
        acc += hf[b*HH + j] * Wout[j] + hb[b*HH + j] * Wout[HH + j];
    out[b] = sigf(acc);
}

// ---------------- launch ----------------
extern "C" void kernel_launch(void* const* d_in, const int* in_sizes, int n_in,
                              void* d_out, int out_size)
{
    (void)in_sizes; (void)n_in; (void)out_size;
    const int*   seq  = (const int*)  d_in[0];
    const float* emb  = (const float*)d_in[1];
    const float* Wihf = (const float*)d_in[2];
    const float* Whhf = (const float*)d_in[3];
    const float* bf   = (const float*)d_in[4];
    const float* Wihb = (const float*)d_in[5];
    const float* Whhb = (const float*)d_in[6];
    const float* bb   = (const float*)d_in[7];
    const float* Wout = (const float*)d_in[8];
    const float* bout = (const float*)d_in[9];
    (void)Whhb;
    float* out = (float*)d_out;

    float *x, *xgf, *gb, *hf, *hb;
    cudaGetSymbolAddress((void**)&x,   g_x);
    cudaGetSymbolAddress((void**)&xgf, g_xg);
    cudaGetSymbolAddress((void**)&gb,  g_gb);
    cudaGetSymbolAddress((void**)&hf,  g_hf);
    cudaGetSymbolAddress((void**)&hb,  g_hb);

    const int SMEM_GEMM = 2 * 128 * 68 * 4;   // 69632
    cudaFuncSetAttribute(k_gemm, cudaFuncAttributeMaxDynamicSharedMemorySize, SMEM_GEMM);

    // 1. embed
    k_embed<<<SQ*BB/4, 128>>>(seq, emb, x);
    // 2. forward input projection xg_f
    dim3 g2(16, SQ*BB/64);
    k_gemm<<<g2, 256, SMEM_GEMM>>>(x, Wihf, bf, xgf);
    // 3. backward first step
    dim3 g2b(16, 1);
    k_gemm<<<g2b, 256, SMEM_GEMM>>>(x + (size_t)(SQ-1)*BB*EE, Wihb, bb, gb);
    k_hback<<<64, 256>>>(gb, hb);
    // 4. sequential forward scan
    k_scan<<<128, 256>>>(xgf, Whhf, hf);
    // 5. output head
    k_out<<<1, 64>>>(hf, hb, Wout, bout, out);
}